// round 7
// baseline (speedup 1.0000x reference)
#include <cuda_runtime.h>
#include <cuda_bf16.h>
#include <math.h>

#define Bsz   4
#define Lsz   4096
#define Esz   1024
#define HEADS 64
#define SPLIT 8
#define CHUNK 512
#define KC    32

#define PART   8320
#define OFF_W  8192

typedef unsigned int u32;

__device__ float g_part[HEADS * SPLIT * PART];
__device__ __nv_bfloat16 g_kvt_h[HEADS * 8192];   // KV^T hi [head][m][f]
__device__ __nv_bfloat16 g_kvt_l[HEADS * 8192];   // KV^T lo
__device__ float g_w[HEADS * 128];

// ---- helpers ---------------------------------------------------------------
__device__ __forceinline__ void mma_bf16(float* c, const u32* a, u32 b0, u32 b1) {
    asm("mma.sync.aligned.m16n8k16.row.col.f32.bf16.bf16.f32 "
        "{%0,%1,%2,%3}, {%4,%5,%6,%7}, {%8,%9}, {%0,%1,%2,%3};"
        : "+f"(c[0]), "+f"(c[1]), "+f"(c[2]), "+f"(c[3])
        : "r"(a[0]), "r"(a[1]), "r"(a[2]), "r"(a[3]), "r"(b0), "r"(b1));
}
__device__ __forceinline__ u32 sh_addr(const void* p) {
    return (u32)__cvta_generic_to_shared(p);
}
__device__ __forceinline__ void ldsm4(u32* r, u32 a) {
    asm volatile("ldmatrix.sync.aligned.m8n8.x4.shared.b16 {%0,%1,%2,%3}, [%4];"
        : "=r"(r[0]), "=r"(r[1]), "=r"(r[2]), "=r"(r[3]) : "r"(a));
}
__device__ __forceinline__ void ldsm4t(u32* r, u32 a) {
    asm volatile("ldmatrix.sync.aligned.m8n8.x4.trans.shared.b16 {%0,%1,%2,%3}, [%4];"
        : "=r"(r[0]), "=r"(r[1]), "=r"(r[2]), "=r"(r[3]) : "r"(a));
}
// split (a,b) -> packed bf16x2 hi + lo planes; a in low half, b in high half
__device__ __forceinline__ void split2(float a, float b, u32& hp, u32& lp) {
    asm("cvt.rn.bf16x2.f32 %0, %1, %2;" : "=r"(hp) : "f"(b), "f"(a));
    float ha = __uint_as_float(hp << 16);
    float hb = __uint_as_float(hp & 0xFFFF0000u);
    asm("cvt.rn.bf16x2.f32 %0, %1, %2;" : "=r"(lp) : "f"(b - hb), "f"(a - ha));
}
__device__ __forceinline__ void bsplit(float x, __nv_bfloat16* ph, __nv_bfloat16* pl) {
    __nv_bfloat16 h = __float2bfloat16(x);
    *ph = h;
    *pl = __float2bfloat16(x - __bfloat162float(h));
}

// ---------------------------------------------------------------------------
// Phase 1: D[f][m] = sum_l X[f][l]*Y[l][m]; 256 thr, 8 warps (16 f-rows each),
// double-buffered token-major staging, bf16-split (hh+hl+lh) MMA.
// ---------------------------------------------------------------------------
#define XSTR 136
#define TSTR 72
#define P1BX (KC * XSTR)
#define P1BT (KC * TSTR)
#define SM1_BYTES ((2*P1BX + 2*P1BT) * 2 * 2 + (512*3 + 16*128) * 4)

__global__ __launch_bounds__(256) void k_phase1(const float* __restrict__ K,
                                                const float* __restrict__ V,
                                                const float* __restrict__ M) {
    extern __shared__ char sm1[];
    __nv_bfloat16* Xh = (__nv_bfloat16*)sm1;
    __nv_bfloat16* Xl = Xh + 2 * P1BX;
    __nv_bfloat16* Th = Xl + 2 * P1BX;
    __nv_bfloat16* Tl = Th + 2 * P1BT;
    float* ssh = (float*)(Tl + 2 * P1BT);
    float* csh = ssh + 512;
    float* msh = csh + 512;
    float* ksp = msh + 512;

    int blk = blockIdx.x;
    int n  = blk >> 3;
    int sp = blk & 7;
    int b = n >> 4, h = n & 15;
    int l0 = sp * CHUNK;

    const float* kb = K + ((size_t)b * Lsz + l0) * Esz + h * 64;
    const float* vb = V + ((size_t)b * Lsz + l0) * Esz + h * 64;
    const float* mb = M + (size_t)b * Lsz + l0;

    int t = threadIdx.x;
    for (int i = t; i < CHUNK; i += 256) {
        int l = l0 + i;
        float ang = 1.5707963267948966f * (float)(l + 1) / (float)Lsz;
        float m = mb[i];
        ssh[i] = sinf(ang) * m;
        csh[i] = cosf(ang) * m;
        msh[i] = m;
    }
    __syncthreads();

    int w = t >> 5, lane = t & 31;
    int gid = lane >> 2, tid = lane & 3;
    int ddg = (t & 15) * 4;
    int pr  = t >> 4;          // 0..15
    int ra = (lane & 7) + ((lane >> 4) & 1) * 8;
    int ca = ((lane >> 3) & 1) * 8;

    float acc[8][4];
    #pragma unroll
    for (int j = 0; j < 8; ++j)
        #pragma unroll
        for (int q = 0; q < 4; ++q) acc[j][q] = 0.f;
    float ksr[4] = {0,0,0,0}, kcr[4] = {0,0,0,0};

    auto stage = [&](int g, int bb) {
        __nv_bfloat16* xh = Xh + bb * P1BX;
        __nv_bfloat16* xl = Xl + bb * P1BX;
        __nv_bfloat16* th = Th + bb * P1BT;
        __nv_bfloat16* tl = Tl + bb * P1BT;
        #pragma unroll
        for (int jj = 0; jj < 2; ++jj) {
            int tok = jj * 16 + pr;
            int li = g * KC + tok;
            float4 k4 = *(const float4*)&kb[(size_t)li * Esz + ddg];
            float4 v4 = *(const float4*)&vb[(size_t)li * Esz + ddg];
            float s = ssh[li], c = csh[li], m = msh[li];
            float rk[4] = { fmaxf(k4.x, 0.f), fmaxf(k4.y, 0.f),
                            fmaxf(k4.z, 0.f), fmaxf(k4.w, 0.f) };
            float sk[4], ck[4], vm[4] = { v4.x * m, v4.y * m, v4.z * m, v4.w * m };
            #pragma unroll
            for (int i = 0; i < 4; ++i) {
                sk[i] = rk[i] * s; ck[i] = rk[i] * c;
                ksr[i] += sk[i];   kcr[i] += ck[i];
            }
            u32 h0, l0_, h1, l1;
            split2(sk[0], sk[1], h0, l0_); split2(sk[2], sk[3], h1, l1);
            *(uint2*)&xh[tok * XSTR + ddg] = make_uint2(h0, h1);
            *(uint2*)&xl[tok * XSTR + ddg] = make_uint2(l0_, l1);
            split2(ck[0], ck[1], h0, l0_); split2(ck[2], ck[3], h1, l1);
            *(uint2*)&xh[tok * XSTR + 64 + ddg] = make_uint2(h0, h1);
            *(uint2*)&xl[tok * XSTR + 64 + ddg] = make_uint2(l0_, l1);
            split2(vm[0], vm[1], h0, l0_); split2(vm[2], vm[3], h1, l1);
            *(uint2*)&th[tok * TSTR + ddg] = make_uint2(h0, h1);
            *(uint2*)&tl[tok * TSTR + ddg] = make_uint2(l0_, l1);
        }
    };

    stage(0, 0);
    __syncthreads();

    const int NG = CHUNK / KC;     // 16
    for (int g = 0; g < NG; ++g) {
        int cur = g & 1;
        if (g + 1 < NG) stage(g + 1, cur ^ 1);

        __nv_bfloat16* xh = Xh + cur * P1BX;
        __nv_bfloat16* xl = Xl + cur * P1BX;
        __nv_bfloat16* th = Th + cur * P1BT;
        __nv_bfloat16* tl = Tl + cur * P1BT;
        #pragma unroll
        for (int ko = 0; ko < KC; ko += 16) {
            u32 ah[4], al[4];
            ldsm4t(ah, sh_addr(&xh[(ko + ra) * XSTR + w * 16 + ca]));
            ldsm4t(al, sh_addr(&xl[(ko + ra) * XSTR + w * 16 + ca]));
            #pragma unroll
            for (int jp = 0; jp < 4; ++jp) {
                u32 bh[4], bl[4];
                ldsm4t(bh, sh_addr(&th[(ko + ra) * TSTR + jp * 16 + ca]));
                ldsm4t(bl, sh_addr(&tl[(ko + ra) * TSTR + jp * 16 + ca]));
                mma_bf16(acc[2 * jp],     ah, bh[0], bh[2]);
                mma_bf16(acc[2 * jp],     ah, bl[0], bl[2]);
                mma_bf16(acc[2 * jp],     al, bh[0], bh[2]);
                mma_bf16(acc[2 * jp + 1], ah, bh[1], bh[3]);
                mma_bf16(acc[2 * jp + 1], ah, bl[1], bl[3]);
                mma_bf16(acc[2 * jp + 1], al, bh[1], bh[3]);
            }
        }
        __syncthreads();
    }

    float* p = g_part + (size_t)blk * PART;
    {
        int r = w * 16 + gid;
        #pragma unroll
        for (int j = 0; j < 8; ++j) {
            int nb = j * 8 + tid * 2;
            *(float2*)&p[r * 64 + nb]       = make_float2(acc[j][0], acc[j][1]);
            *(float2*)&p[(r + 8) * 64 + nb] = make_float2(acc[j][2], acc[j][3]);
        }
    }
    #pragma unroll
    for (int i = 0; i < 4; ++i) {
        ksp[pr * 128 + ddg + i]      = ksr[i];
        ksp[pr * 128 + 64 + ddg + i] = kcr[i];
    }
    __syncthreads();
    if (t < 128) {
        float s = 0.f;
        #pragma unroll
        for (int r = 0; r < 16; ++r) s += ksp[r * 128 + t];
        p[OFF_W + t] = s;
    }
}

// ---------------------------------------------------------------------------
// Reduce: sum SPLIT fp32 partials; emit KV^T bf16 hi/lo planes + fp32 w.
// ---------------------------------------------------------------------------
__global__ __launch_bounds__(256) void k_reduce() {
    int blk = blockIdx.x;
    int n = blk >> 2;
    int sl = blk & 3;
    int t = threadIdx.x;
    for (int idx = sl * 2048 + t; idx < sl * 2048 + 2048; idx += 256) {
        int f = idx >> 6, m = idx & 63;
        float s = 0.f;
        #pragma unroll
        for (int sp = 0; sp < SPLIT; ++sp)
            s += g_part[(size_t)(n * SPLIT + sp) * PART + idx];
        __nv_bfloat16 hh, ll;
        bsplit(s, &hh, &ll);
        g_kvt_h[(size_t)n * 8192 + m * 128 + f] = hh;
        g_kvt_l[(size_t)n * 8192 + m * 128 + f] = ll;
    }
    if (sl == 0 && t < 128) {
        float s = 0.f;
        #pragma unroll
        for (int sp = 0; sp < SPLIT; ++sp)
            s += g_part[(size_t)(n * SPLIT + sp) * PART + OFF_W + t];
        g_w[n * 128 + t] = s;
    }
}

// ---------------------------------------------------------------------------
// Phase 2: out[l][m] = z_l * (Rq[l] @ KV)[m]; 128-token tiles, 256 threads.
// ---------------------------------------------------------------------------
#define TT   128
#define FS2  136
#define X2H_OFF  0
#define X2L_OFF  (TT * FS2 * 2)
#define KH_OFF   (2 * TT * FS2 * 2)
#define KL_OFF   (2 * TT * FS2 * 2 + 64 * FS2 * 2)
#define FP_OFF   (2 * TT * FS2 * 2 + 2 * 64 * FS2 * 2)
#define SM2_BYTES (FP_OFF + (128 + TT * 16 + TT * 3) * 4)

__global__ __launch_bounds__(256) void k_phase2(const float* __restrict__ Q,
                                                float* __restrict__ O) {
    extern __shared__ char sm2[];
    __nv_bfloat16* X2h = (__nv_bfloat16*)(sm2 + X2H_OFF);
    __nv_bfloat16* X2l = (__nv_bfloat16*)(sm2 + X2L_OFF);
    __nv_bfloat16* Kh  = (__nv_bfloat16*)(sm2 + KH_OFF);
    __nv_bfloat16* Kl  = (__nv_bfloat16*)(sm2 + KL_OFF);
    float* wsh = (float*)(sm2 + FP_OFF);
    float* zp  = wsh + 128;
    float* zsh = zp + TT * 16;
    float* ssh = zsh + TT;
    float* csh = ssh + TT;

    int blk = blockIdx.x;
    int n = blk >> 5;
    int tile = blk & 31;
    int b = n >> 4, h = n & 15;
    int l0 = tile * TT;

    const float* qb = Q + ((size_t)b * Lsz + l0) * Esz + h * 64;
    int t = threadIdx.x;

    if (t < 128) {
        wsh[t] = g_w[n * 128 + t];
        int l = l0 + t;
        float ang = 1.5707963267948966f * (float)(l + 1) / (float)Lsz;
        ssh[t] = sinf(ang);
        csh[t] = cosf(ang);
    }
    for (int idx = t; idx < 2048; idx += 256) {
        int mr = idx >> 5, c = idx & 31;
        *(uint2*)&Kh[mr * FS2 + c * 4] =
            *(const uint2*)&g_kvt_h[(size_t)n * 8192 + mr * 128 + c * 4];
        *(uint2*)&Kl[mr * FS2 + c * 4] =
            *(const uint2*)&g_kvt_l[(size_t)n * 8192 + mr * 128 + c * 4];
    }
    __syncthreads();

    // stage Rq (bf16 split) + z partials
    #pragma unroll
    for (int j = 0; j < 8; ++j) {
        int e4 = j * 256 + t;
        int tok = e4 >> 4;
        int ddg = (e4 & 15) * 4;
        float s = ssh[tok], c = csh[tok];
        float4 q4 = *(const float4*)&qb[(size_t)tok * Esz + ddg];
        float rq[4] = { fmaxf(q4.x, 0.f), fmaxf(q4.y, 0.f),
                        fmaxf(q4.z, 0.f), fmaxf(q4.w, 0.f) };
        float xs[4], xc[4];
        float zpart = 0.f;
        #pragma unroll
        for (int i = 0; i < 4; ++i) {
            xs[i] = rq[i] * s; xc[i] = rq[i] * c;
            zpart += xs[i] * wsh[ddg + i] + xc[i] * wsh[64 + ddg + i];
        }
        u32 h0, l0_, h1, l1;
        split2(xs[0], xs[1], h0, l0_); split2(xs[2], xs[3], h1, l1);
        *(uint2*)&X2h[tok * FS2 + ddg] = make_uint2(h0, h1);
        *(uint2*)&X2l[tok * FS2 + ddg] = make_uint2(l0_, l1);
        split2(xc[0], xc[1], h0, l0_); split2(xc[2], xc[3], h1, l1);
        *(uint2*)&X2h[tok * FS2 + 64 + ddg] = make_uint2(h0, h1);
        *(uint2*)&X2l[tok * FS2 + 64 + ddg] = make_uint2(l0_, l1);
        zp[tok * 16 + (e4 & 15)] = zpart;
    }
    __syncthreads();
    if (t < TT) {
        float a = 0.f;
        #pragma unroll
        for (int g = 0; g < 16; ++g) a += zp[t * 16 + g];
        zsh[t] = 1.f / fmaxf(a, 1e-6f);
    }
    __syncthreads();

    int w = t >> 5, lane = t & 31;
    int gid = lane >> 2, tid = lane & 3;
    int t0 = w * 16;
    int rn = lane & 15;
    int cn = ((lane >> 4) & 1) * 8;

    float acc[8][4];
    #pragma unroll
    for (int j = 0; j < 8; ++j)
        #pragma unroll
        for (int q = 0; q < 4; ++q) acc[j][q] = 0.f;

    #pragma unroll
    for (int ko = 0; ko < 128; ko += 16) {
        u32 ah[4], al[4];
        ldsm4(ah, sh_addr(&X2h[(t0 + rn) * FS2 + ko + cn]));
        ldsm4(al, sh_addr(&X2l[(t0 + rn) * FS2 + ko + cn]));
        #pragma unroll
        for (int jp = 0; jp < 4; ++jp) {
            u32 bh[4], bl[4];
            ldsm4(bh, sh_addr(&Kh[(jp * 16 + rn) * FS2 + ko + cn]));
            ldsm4(bl, sh_addr(&Kl[(jp * 16 + rn) * FS2 + ko + cn]));
            mma_bf16(acc[2 * jp],     ah, bh[0], bh[2]);
            mma_bf16(acc[2 * jp],     ah, bl[0], bl[2]);
            mma_bf16(acc[2 * jp],     al, bh[0], bh[2]);
            mma_bf16(acc[2 * jp + 1], ah, bh[1], bh[3]);
            mma_bf16(acc[2 * jp + 1], ah, bl[1], bl[3]);
            mma_bf16(acc[2 * jp + 1], al, bh[1], bh[3]);
        }
    }

    float* ob = O + ((size_t)n * Lsz + l0) * 64;
    int r1 = t0 + gid;
    float z1 = zsh[r1], z2 = zsh[r1 + 8];
    #pragma unroll
    for (int j = 0; j < 8; ++j) {
        int nb = j * 8 + tid * 2;
        *(float2*)&ob[(size_t)r1 * 64 + nb] =
            make_float2(acc[j][0] * z1, acc[j][1] * z1);
        *(float2*)&ob[(size_t)(r1 + 8) * 64 + nb] =
            make_float2(acc[j][2] * z2, acc[j][3] * z2);
    }
}

// ---------------------------------------------------------------------------
extern "C" void kernel_launch(void* const* d_in, const int* in_sizes, int n_in,
                              void* d_out, int out_size) {
    const float* q = (const float*)d_in[0];
    const float* k = (const float*)d_in[1];
    const float* v = (const float*)d_in[2];
    const float* m = (const float*)d_in[3];
    float* out = (float*)d_out;

    cudaFuncSetAttribute(k_phase1, cudaFuncAttributeMaxDynamicSharedMemorySize,
                         SM1_BYTES);
    cudaFuncSetAttribute(k_phase2, cudaFuncAttributeMaxDynamicSharedMemorySize,
                         SM2_BYTES);

    k_phase1<<<HEADS * SPLIT, 256, SM1_BYTES>>>(k, v, m);
    k_reduce<<<HEADS * 4, 256>>>();
    k_phase2<<<HEADS * 32, 256, SM2_BYTES>>>(q, out);
}

// round 8
// speedup vs baseline: 1.0178x; 1.0178x over previous
#include <cuda_runtime.h>
#include <cuda_fp16.h>
#include <math.h>

#define Bsz   4
#define Lsz   4096
#define Esz   1024
#define HEADS 64
#define SPLIT 8
#define CHUNK 512
#define KC    32

#define PART   8320
#define OFF_W  8192

typedef unsigned int u32;

__device__ float g_part[HEADS * SPLIT * PART];
__device__ __half g_kvt_h[HEADS * 8192];   // KV^T hi [head][m][f]
__device__ __half g_kvt_l[HEADS * 8192];   // KV^T lo
__device__ float g_w[HEADS * 128];

// ---- helpers ---------------------------------------------------------------
__device__ __forceinline__ void mma_f16(float* c, const u32* a, u32 b0, u32 b1) {
    asm("mma.sync.aligned.m16n8k16.row.col.f32.f16.f16.f32 "
        "{%0,%1,%2,%3}, {%4,%5,%6,%7}, {%8,%9}, {%0,%1,%2,%3};"
        : "+f"(c[0]), "+f"(c[1]), "+f"(c[2]), "+f"(c[3])
        : "r"(a[0]), "r"(a[1]), "r"(a[2]), "r"(a[3]), "r"(b0), "r"(b1));
}
__device__ __forceinline__ u32 sh_addr(const void* p) {
    return (u32)__cvta_generic_to_shared(p);
}
__device__ __forceinline__ void ldsm4(u32* r, u32 a) {
    asm volatile("ldmatrix.sync.aligned.m8n8.x4.shared.b16 {%0,%1,%2,%3}, [%4];"
        : "=r"(r[0]), "=r"(r[1]), "=r"(r[2]), "=r"(r[3]) : "r"(a));
}
__device__ __forceinline__ void ldsm4t(u32* r, u32 a) {
    asm volatile("ldmatrix.sync.aligned.m8n8.x4.trans.shared.b16 {%0,%1,%2,%3}, [%4];"
        : "=r"(r[0]), "=r"(r[1]), "=r"(r[2]), "=r"(r[3]) : "r"(a));
}
// pack two floats to f16x2 (a -> low half)
__device__ __forceinline__ u32 pk16(float a, float b) {
    u32 r;
    asm("cvt.rn.f16x2.f32 %0, %1, %2;" : "=r"(r) : "f"(b), "f"(a));
    return r;
}
// 2-plane fp16 split of a pair
__device__ __forceinline__ void split16(float a, float b, u32& hp, u32& lp) {
    hp = pk16(a, b);
    __half2 h = *(__half2*)&hp;
    float2 hf = __half22float2(h);
    lp = pk16(a - hf.x, b - hf.y);
}

// ---------------------------------------------------------------------------
// Phase 1: D[f][m] = sum_l X[f][l]*Y[l][m]
//   X = [s*mask*relu(k) ; c*mask*relu(k)] (single fp16 plane)
//   Y = mask*v (2-plane fp16 hi/lo)
//   2 MMAs per tile: ah*bh + ah*bl  (error = fp16-rounding of X only)
//   w[f] = exact fp32 side sum.
// ---------------------------------------------------------------------------
#define XSTR 136
#define TSTR 72

__global__ __launch_bounds__(128) void k_phase1(const float* __restrict__ K,
                                                const float* __restrict__ V,
                                                const float* __restrict__ M) {
    int blk = blockIdx.x;
    int n  = blk >> 3;
    int sp = blk & 7;
    int b = n >> 4, h = n & 15;
    int l0 = sp * CHUNK;

    const float* kb = K + ((size_t)b * Lsz + l0) * Esz + h * 64;
    const float* vb = V + ((size_t)b * Lsz + l0) * Esz + h * 64;
    const float* mb = M + (size_t)b * Lsz + l0;

    __shared__ __half Xh[KC * XSTR];
    __shared__ __half Th[KC * TSTR], Tl[KC * TSTR];
    __shared__ float ssh[CHUNK], csh[CHUNK], msh[CHUNK];
    __shared__ float ksp[8 * 128];

    int t = threadIdx.x;
    for (int i = t; i < CHUNK; i += 128) {
        int l = l0 + i;
        float ang = 1.5707963267948966f * (float)(l + 1) / (float)Lsz;
        float m = mb[i];
        ssh[i] = sinf(ang) * m;
        csh[i] = cosf(ang) * m;
        msh[i] = m;
    }

    int w = t >> 5, lane = t & 31;
    int gid = lane >> 2, tid = lane & 3;
    int rb = w * 32;
    int ddg = (t & 15) * 4;
    int pr  = t >> 4;          // 0..7
    int ra = (lane & 7) + ((lane >> 4) & 1) * 8;
    int ca = ((lane >> 3) & 1) * 8;

    float acc[2][8][4];
    #pragma unroll
    for (int i = 0; i < 2; ++i)
        #pragma unroll
        for (int j = 0; j < 8; ++j)
            #pragma unroll
            for (int q = 0; q < 4; ++q) acc[i][j][q] = 0.f;
    float ksr[4] = {0,0,0,0}, kcr[4] = {0,0,0,0};

    for (int g = 0; g < CHUNK / KC; ++g) {
        __syncthreads();
        // stage KC=32 tokens, token-major
        #pragma unroll
        for (int jj = 0; jj < 4; ++jj) {
            int tok = jj * 8 + pr;
            int li = g * KC + tok;
            float4 k4 = *(const float4*)&kb[(size_t)li * Esz + ddg];
            float4 v4 = *(const float4*)&vb[(size_t)li * Esz + ddg];
            float s = ssh[li], c = csh[li], m = msh[li];
            float rk[4] = { fmaxf(k4.x, 0.f), fmaxf(k4.y, 0.f),
                            fmaxf(k4.z, 0.f), fmaxf(k4.w, 0.f) };
            float sk[4], ck[4], vm[4] = { v4.x * m, v4.y * m, v4.z * m, v4.w * m };
            #pragma unroll
            for (int i = 0; i < 4; ++i) {
                sk[i] = rk[i] * s; ck[i] = rk[i] * c;
                ksr[i] += sk[i];   kcr[i] += ck[i];
            }
            *(uint2*)&Xh[tok * XSTR + ddg] =
                make_uint2(pk16(sk[0], sk[1]), pk16(sk[2], sk[3]));
            *(uint2*)&Xh[tok * XSTR + 64 + ddg] =
                make_uint2(pk16(ck[0], ck[1]), pk16(ck[2], ck[3]));
            u32 h0, lo0, h1, lo1;
            split16(vm[0], vm[1], h0, lo0);
            split16(vm[2], vm[3], h1, lo1);
            *(uint2*)&Th[tok * TSTR + ddg] = make_uint2(h0, h1);
            *(uint2*)&Tl[tok * TSTR + ddg] = make_uint2(lo0, lo1);
        }
        __syncthreads();

        #pragma unroll
        for (int ko = 0; ko < KC; ko += 16) {
            u32 ah[2][4];
            #pragma unroll
            for (int i = 0; i < 2; ++i)
                ldsm4t(ah[i], sh_addr(&Xh[(ko + ra) * XSTR + rb + i * 16 + ca]));
            #pragma unroll
            for (int jp = 0; jp < 4; ++jp) {
                u32 bh[4], bl[4];
                ldsm4t(bh, sh_addr(&Th[(ko + ra) * TSTR + jp * 16 + ca]));
                ldsm4t(bl, sh_addr(&Tl[(ko + ra) * TSTR + jp * 16 + ca]));
                #pragma unroll
                for (int i = 0; i < 2; ++i) {
                    mma_f16(acc[i][2 * jp],     ah[i], bh[0], bh[2]);
                    mma_f16(acc[i][2 * jp],     ah[i], bl[0], bl[2]);
                    mma_f16(acc[i][2 * jp + 1], ah[i], bh[1], bh[3]);
                    mma_f16(acc[i][2 * jp + 1], ah[i], bl[1], bl[3]);
                }
            }
        }
    }

    float* p = g_part + (size_t)blk * PART;
    #pragma unroll
    for (int i = 0; i < 2; ++i) {
        int r = rb + 16 * i + gid;
        #pragma unroll
        for (int j = 0; j < 8; ++j) {
            int nb = j * 8 + tid * 2;
            *(float2*)&p[r * 64 + nb]       = make_float2(acc[i][j][0], acc[i][j][1]);
            *(float2*)&p[(r + 8) * 64 + nb] = make_float2(acc[i][j][2], acc[i][j][3]);
        }
    }
    #pragma unroll
    for (int i = 0; i < 4; ++i) {
        ksp[pr * 128 + ddg + i]      = ksr[i];
        ksp[pr * 128 + 64 + ddg + i] = kcr[i];
    }
    __syncthreads();
    {
        float s = 0.f;
        #pragma unroll
        for (int r = 0; r < 8; ++r) s += ksp[r * 128 + t];
        p[OFF_W + t] = s;
    }
}

// ---------------------------------------------------------------------------
// Reduce: sum SPLIT fp32 partials; emit KV^T fp16 hi/lo planes + fp32 w.
// ---------------------------------------------------------------------------
__global__ __launch_bounds__(256) void k_reduce() {
    int blk = blockIdx.x;
    int n = blk >> 2;
    int sl = blk & 3;
    int t = threadIdx.x;
    for (int idx = sl * 2048 + t; idx < sl * 2048 + 2048; idx += 256) {
        int f = idx >> 6, m = idx & 63;
        float s = 0.f;
        #pragma unroll
        for (int sp = 0; sp < SPLIT; ++sp)
            s += g_part[(size_t)(n * SPLIT + sp) * PART + idx];
        __half hh = __float2half_rn(s);
        __half ll = __float2half_rn(s - __half2float(hh));
        g_kvt_h[(size_t)n * 8192 + m * 128 + f] = hh;
        g_kvt_l[(size_t)n * 8192 + m * 128 + f] = ll;
    }
    if (sl == 0 && t < 128) {
        float s = 0.f;
        #pragma unroll
        for (int sp = 0; sp < SPLIT; ++sp)
            s += g_part[(size_t)(n * SPLIT + sp) * PART + OFF_W + t];
        g_w[n * 128 + t] = s;
    }
}

// ---------------------------------------------------------------------------
// Phase 2: out[l][m] = z_l * (Rq[l] @ KV)[m]
//   Rq single fp16 plane; KV 2-plane fp16; 2 MMAs: ah*bh + ah*bl.
//   z exact fp32 (computed pre-rounding).
// ---------------------------------------------------------------------------
#define FS2 136
#define X2H_OFF  0
#define KH_OFF   (64 * FS2 * 2)
#define KL_OFF   (2 * 64 * FS2 * 2)
#define FP_OFF   (3 * 64 * FS2 * 2)
#define SM2_BYTES (FP_OFF + (128 + 1024 + 64 * 3) * 4)

__global__ __launch_bounds__(128) void k_phase2(const float* __restrict__ Q,
                                                float* __restrict__ O) {
    extern __shared__ char sm2[];
    __half* X2h = (__half*)(sm2 + X2H_OFF);
    __half* Kh  = (__half*)(sm2 + KH_OFF);
    __half* Kl  = (__half*)(sm2 + KL_OFF);
    float* wsh = (float*)(sm2 + FP_OFF);
    float* zp  = wsh + 128;
    float* zsh = zp + 1024;
    float* ssh = zsh + 64;
    float* csh = ssh + 64;

    int blk = blockIdx.x;
    int n = blk >> 6;
    int tile = blk & 63;
    int b = n >> 4, h = n & 15;
    int l0 = tile * 64;

    const float* qb = Q + ((size_t)b * Lsz + l0) * Esz + h * 64;
    int t = threadIdx.x;

    if (t < 128) wsh[t] = g_w[n * 128 + t];
    if (t < 64) {
        int l = l0 + t;
        float ang = 1.5707963267948966f * (float)(l + 1) / (float)Lsz;
        ssh[t] = sinf(ang);
        csh[t] = cosf(ang);
    }
    for (int idx = t; idx < 2048; idx += 128) {
        int mr = idx >> 5, c = idx & 31;
        *(uint2*)&Kh[mr * FS2 + c * 4] =
            *(const uint2*)&g_kvt_h[(size_t)n * 8192 + mr * 128 + c * 4];
        *(uint2*)&Kl[mr * FS2 + c * 4] =
            *(const uint2*)&g_kvt_l[(size_t)n * 8192 + mr * 128 + c * 4];
    }
    __syncthreads();

    int ddg = (t & 15) * 4;
    #pragma unroll
    for (int j = 0; j < 8; ++j) {
        int e4 = j * 128 + t;
        int tok = e4 >> 4;
        float s = ssh[tok], c = csh[tok];
        float4 q4 = *(const float4*)&qb[(size_t)tok * Esz + ddg];
        float rq[4] = { fmaxf(q4.x, 0.f), fmaxf(q4.y, 0.f),
                        fmaxf(q4.z, 0.f), fmaxf(q4.w, 0.f) };
        float xs[4], xc[4];
        float zpart = 0.f;
        #pragma unroll
        for (int i = 0; i < 4; ++i) {
            xs[i] = rq[i] * s; xc[i] = rq[i] * c;
            zpart += xs[i] * wsh[ddg + i] + xc[i] * wsh[64 + ddg + i];
        }
        *(uint2*)&X2h[tok * FS2 + ddg] =
            make_uint2(pk16(xs[0], xs[1]), pk16(xs[2], xs[3]));
        *(uint2*)&X2h[tok * FS2 + 64 + ddg] =
            make_uint2(pk16(xc[0], xc[1]), pk16(xc[2], xc[3]));
        zp[tok * 16 + (t & 15)] = zpart;
    }
    __syncthreads();
    if (t < 64) {
        float a = 0.f;
        #pragma unroll
        for (int g = 0; g < 16; ++g) a += zp[t * 16 + g];
        zsh[t] = 1.f / fmaxf(a, 1e-6f);
    }
    __syncthreads();

    int w = t >> 5, lane = t & 31;
    int gid = lane >> 2, tid = lane & 3;
    int t0 = w * 16;
    int rn = lane & 15;
    int cn = ((lane >> 4) & 1) * 8;

    float acc[8][4];
    #pragma unroll
    for (int j = 0; j < 8; ++j)
        #pragma unroll
        for (int q = 0; q < 4; ++q) acc[j][q] = 0.f;

    #pragma unroll
    for (int ko = 0; ko < 128; ko += 16) {
        u32 ah[4];
        ldsm4(ah, sh_addr(&X2h[(t0 + rn) * FS2 + ko + cn]));
        #pragma unroll
        for (int jp = 0; jp < 4; ++jp) {
            u32 bh[4], bl[4];
            ldsm4(bh, sh_addr(&Kh[(jp * 16 + rn) * FS2 + ko + cn]));
            ldsm4(bl, sh_addr(&Kl[(jp * 16 + rn) * FS2 + ko + cn]));
            mma_f16(acc[2 * jp],     ah, bh[0], bh[2]);
            mma_f16(acc[2 * jp],     ah, bl[0], bl[2]);
            mma_f16(acc[2 * jp + 1], ah, bh[1], bh[3]);
            mma_f16(acc[2 * jp + 1], ah, bl[1], bl[3]);
        }
    }

    float* ob = O + ((size_t)n * Lsz + l0) * 64;
    int r1 = t0 + gid;
    float z1 = zsh[r1], z2 = zsh[r1 + 8];
    #pragma unroll
    for (int j = 0; j < 8; ++j) {
        int nb = j * 8 + tid * 2;
        *(float2*)&ob[(size_t)r1 * 64 + nb] =
            make_float2(acc[j][0] * z1, acc[j][1] * z1);
        *(float2*)&ob[(size_t)(r1 + 8) * 64 + nb] =
            make_float2(acc[j][2] * z2, acc[j][3] * z2);
    }
}

// ---------------------------------------------------------------------------
extern "C" void kernel_launch(void* const* d_in, const int* in_sizes, int n_in,
                              void* d_out, int out_size) {
    const float* q = (const float*)d_in[0];
    const float* k = (const float*)d_in[1];
    const float* v = (const float*)d_in[2];
    const float* m = (const float*)d_in[3];
    float* out = (float*)d_out;

    cudaFuncSetAttribute(k_phase2, cudaFuncAttributeMaxDynamicSharedMemorySize,
                         SM2_BYTES);

    k_phase1<<<HEADS * SPLIT, 128>>>(k, v, m);
    k_reduce<<<HEADS * 4, 256>>>();
    k_phase2<<<HEADS * 64, 128, SM2_BYTES>>>(q, out);
}

// round 9
// speedup vs baseline: 1.7969x; 1.7654x over previous
#include <cuda_runtime.h>
#include <cuda_fp16.h>
#include <math.h>

#define Bsz   4
#define Lsz   4096
#define Esz   1024
#define HEADS 64
#define SPLIT 8
#define CHUNK 512
#define KC    32
#define NG    (CHUNK / KC)

#define PART   8320
#define OFF_W  8192

typedef unsigned int u32;

__device__ float g_part[HEADS * SPLIT * PART];
__device__ __half g_kvt_h[HEADS * 8192];   // KV^T hi [head][m][f]
__device__ __half g_kvt_l[HEADS * 8192];   // KV^T lo
__device__ float g_w[HEADS * 128];

// ---- helpers ---------------------------------------------------------------
__device__ __forceinline__ void mma_f16(float* c, const u32* a, u32 b0, u32 b1) {
    asm("mma.sync.aligned.m16n8k16.row.col.f32.f16.f16.f32 "
        "{%0,%1,%2,%3}, {%4,%5,%6,%7}, {%8,%9}, {%0,%1,%2,%3};"
        : "+f"(c[0]), "+f"(c[1]), "+f"(c[2]), "+f"(c[3])
        : "r"(a[0]), "r"(a[1]), "r"(a[2]), "r"(a[3]), "r"(b0), "r"(b1));
}
__device__ __forceinline__ u32 sh_addr(const void* p) {
    return (u32)__cvta_generic_to_shared(p);
}
__device__ __forceinline__ void ldsm4(u32* r, u32 a) {
    asm volatile("ldmatrix.sync.aligned.m8n8.x4.shared.b16 {%0,%1,%2,%3}, [%4];"
        : "=r"(r[0]), "=r"(r[1]), "=r"(r[2]), "=r"(r[3]) : "r"(a));
}
__device__ __forceinline__ void ldsm4t(u32* r, u32 a) {
    asm volatile("ldmatrix.sync.aligned.m8n8.x4.trans.shared.b16 {%0,%1,%2,%3}, [%4];"
        : "=r"(r[0]), "=r"(r[1]), "=r"(r[2]), "=r"(r[3]) : "r"(a));
}
__device__ __forceinline__ u32 pk16(float a, float b) {
    u32 r;
    asm("cvt.rn.f16x2.f32 %0, %1, %2;" : "=r"(r) : "f"(b), "f"(a));
    return r;
}
__device__ __forceinline__ void split16(float a, float b, u32& hp, u32& lp) {
    hp = pk16(a, b);
    __half2 h = *(__half2*)&hp;
    float2 hf = __half22float2(h);
    lp = pk16(a - hf.x, b - hf.y);
}
#define BARS(id) asm volatile("bar.sync %0, 256;"   :: "r"(id) : "memory")
#define BARA(id) asm volatile("bar.arrive %0, 256;" :: "r"(id) : "memory")

// ---------------------------------------------------------------------------
// Phase 1, warp-specialized: warps 0-3 stage (LDG + feature-map + fp16 cvt),
// warps 4-7 consume (ldsm + HMMA). 2-deep ring, named-barrier handshake.
//   X = [s*mask*relu(k) ; c*mask*relu(k)] single fp16 plane
//   Y = mask*v, 2-plane fp16 (hi+lo)
//   D = X @ Y with 2 MMAs per tile; w exact fp32 side-sum by producers.
// ---------------------------------------------------------------------------
#define XSTR 136
#define TSTR 72

__global__ __launch_bounds__(256) void k_phase1(const float* __restrict__ K,
                                                const float* __restrict__ V,
                                                const float* __restrict__ M) {
    __shared__ __half Xh[2 * KC * XSTR];
    __shared__ __half Th[2 * KC * TSTR], Tl[2 * KC * TSTR];
    __shared__ float ssh[CHUNK], csh[CHUNK], msh[CHUNK];
    __shared__ float ksp[8 * 128];

    int blk = blockIdx.x;
    int n  = blk >> 3;
    int sp = blk & 7;
    int b = n >> 4, h = n & 15;
    int l0 = sp * CHUNK;

    const float* kb = K + ((size_t)b * Lsz + l0) * Esz + h * 64;
    const float* vb = V + ((size_t)b * Lsz + l0) * Esz + h * 64;
    const float* mb = M + (size_t)b * Lsz + l0;

    int t = threadIdx.x;
    for (int i = t; i < CHUNK; i += 256) {
        int l = l0 + i;
        float ang = 1.5707963267948966f * (float)(l + 1) / (float)Lsz;
        float m = mb[i];
        ssh[i] = sinf(ang) * m;
        csh[i] = cosf(ang) * m;
        msh[i] = m;
    }
    __syncthreads();

    float* p = g_part + (size_t)blk * PART;

    if (t < 128) {
        // ------------------ producer warps ------------------
        int ddg = (t & 15) * 4;
        int pr  = t >> 4;          // 0..7
        float ksr[4] = {0,0,0,0}, kcr[4] = {0,0,0,0};

        for (int g = 0; g < NG; ++g) {
            int bb = g & 1;
            if (g >= 2) BARS(3 + bb);          // wait buffer empty
            __half* xh = Xh + bb * KC * XSTR;
            __half* th = Th + bb * KC * TSTR;
            __half* tl = Tl + bb * KC * TSTR;
            #pragma unroll
            for (int jj = 0; jj < 4; ++jj) {
                int tok = jj * 8 + pr;
                int li = g * KC + tok;
                float4 k4 = *(const float4*)&kb[(size_t)li * Esz + ddg];
                float4 v4 = *(const float4*)&vb[(size_t)li * Esz + ddg];
                float s = ssh[li], c = csh[li], m = msh[li];
                float rk[4] = { fmaxf(k4.x, 0.f), fmaxf(k4.y, 0.f),
                                fmaxf(k4.z, 0.f), fmaxf(k4.w, 0.f) };
                float sk[4], ck[4], vm[4] = { v4.x*m, v4.y*m, v4.z*m, v4.w*m };
                #pragma unroll
                for (int i = 0; i < 4; ++i) {
                    sk[i] = rk[i] * s; ck[i] = rk[i] * c;
                    ksr[i] += sk[i];   kcr[i] += ck[i];
                }
                *(uint2*)&xh[tok * XSTR + ddg] =
                    make_uint2(pk16(sk[0], sk[1]), pk16(sk[2], sk[3]));
                *(uint2*)&xh[tok * XSTR + 64 + ddg] =
                    make_uint2(pk16(ck[0], ck[1]), pk16(ck[2], ck[3]));
                u32 h0, lo0, h1, lo1;
                split16(vm[0], vm[1], h0, lo0);
                split16(vm[2], vm[3], h1, lo1);
                *(uint2*)&th[tok * TSTR + ddg] = make_uint2(h0, h1);
                *(uint2*)&tl[tok * TSTR + ddg] = make_uint2(lo0, lo1);
            }
            __threadfence_block();
            BARA(1 + bb);                      // signal buffer full
        }
        #pragma unroll
        for (int i = 0; i < 4; ++i) {
            ksp[pr * 128 + ddg + i]      = ksr[i];
            ksp[pr * 128 + 64 + ddg + i] = kcr[i];
        }
    } else {
        // ------------------ consumer warps ------------------
        int t2 = t - 128;
        int w = t2 >> 5, lane = t2 & 31;
        int gid = lane >> 2, tid = lane & 3;
        int rb = w * 32;
        int ra = (lane & 7) + ((lane >> 4) & 1) * 8;
        int ca = ((lane >> 3) & 1) * 8;

        float acc[2][8][4];
        #pragma unroll
        for (int i = 0; i < 2; ++i)
            #pragma unroll
            for (int j = 0; j < 8; ++j)
                #pragma unroll
                for (int q = 0; q < 4; ++q) acc[i][j][q] = 0.f;

        for (int g = 0; g < NG; ++g) {
            int bb = g & 1;
            BARS(1 + bb);                      // wait buffer full
            __half* xh = Xh + bb * KC * XSTR;
            __half* th = Th + bb * KC * TSTR;
            __half* tl = Tl + bb * KC * TSTR;
            #pragma unroll
            for (int ko = 0; ko < KC; ko += 16) {
                u32 ah[2][4];
                #pragma unroll
                for (int i = 0; i < 2; ++i)
                    ldsm4t(ah[i], sh_addr(&xh[(ko + ra) * XSTR + rb + i * 16 + ca]));
                #pragma unroll
                for (int jp = 0; jp < 4; ++jp) {
                    u32 bh[4], bl[4];
                    ldsm4t(bh, sh_addr(&th[(ko + ra) * TSTR + jp * 16 + ca]));
                    ldsm4t(bl, sh_addr(&tl[(ko + ra) * TSTR + jp * 16 + ca]));
                    #pragma unroll
                    for (int i = 0; i < 2; ++i) {
                        mma_f16(acc[i][2 * jp],     ah[i], bh[0], bh[2]);
                        mma_f16(acc[i][2 * jp],     ah[i], bl[0], bl[2]);
                        mma_f16(acc[i][2 * jp + 1], ah[i], bh[1], bh[3]);
                        mma_f16(acc[i][2 * jp + 1], ah[i], bl[1], bl[3]);
                    }
                }
            }
            BARA(3 + bb);                      // signal buffer empty
        }
        #pragma unroll
        for (int i = 0; i < 2; ++i) {
            int r = rb + 16 * i + gid;
            #pragma unroll
            for (int j = 0; j < 8; ++j) {
                int nb = j * 8 + tid * 2;
                *(float2*)&p[r * 64 + nb]       = make_float2(acc[i][j][0], acc[i][j][1]);
                *(float2*)&p[(r + 8) * 64 + nb] = make_float2(acc[i][j][2], acc[i][j][3]);
            }
        }
    }
    __syncthreads();
    if (t < 128) {
        float s = 0.f;
        #pragma unroll
        for (int r = 0; r < 8; ++r) s += ksp[r * 128 + t];
        p[OFF_W + t] = s;
    }
}

// ---------------------------------------------------------------------------
// Reduce: sum SPLIT fp32 partials; emit KV^T fp16 hi/lo planes + fp32 w.
// ---------------------------------------------------------------------------
__global__ __launch_bounds__(256) void k_reduce() {
    int blk = blockIdx.x;
    int n = blk >> 2;
    int sl = blk & 3;
    int t = threadIdx.x;
    for (int idx = sl * 2048 + t; idx < sl * 2048 + 2048; idx += 256) {
        int f = idx >> 6, m = idx & 63;
        float s = 0.f;
        #pragma unroll
        for (int sp = 0; sp < SPLIT; ++sp)
            s += g_part[(size_t)(n * SPLIT + sp) * PART + idx];
        __half hh = __float2half_rn(s);
        __half ll = __float2half_rn(s - __half2float(hh));
        g_kvt_h[(size_t)n * 8192 + m * 128 + f] = hh;
        g_kvt_l[(size_t)n * 8192 + m * 128 + f] = ll;
    }
    if (sl == 0 && t < 128) {
        float s = 0.f;
        #pragma unroll
        for (int sp = 0; sp < SPLIT; ++sp)
            s += g_part[(size_t)(n * SPLIT + sp) * PART + OFF_W + t];
        g_w[n * 128 + t] = s;
    }
}

// ---------------------------------------------------------------------------
// Phase 2: out[l][m] = z_l * (Rq[l] @ KV)[m]
// 256-token blocks, 256 threads, 8 warps as 4 (tok) x 2 (m): each warp
// 64 tok x 32 m -> ldsm:MMA ratio 0.25. Rq single fp16 plane; KV 2-plane.
// ---------------------------------------------------------------------------
#define TT2  256
#define FS2  136
#define X2H_OFF  0
#define KH_OFF   (TT2 * FS2 * 2)
#define KL_OFF   (KH_OFF + 64 * FS2 * 2)
#define FP_OFF   (KL_OFF + 64 * FS2 * 2)
// floats: wsh[128] zp[TT2*16] zsh[TT2] ssh[TT2] csh[TT2]
#define SM2_BYTES (FP_OFF + (128 + TT2 * 16 + TT2 * 3) * 4)

__global__ __launch_bounds__(256) void k_phase2(const float* __restrict__ Q,
                                                float* __restrict__ O) {
    extern __shared__ char sm2[];
    __half* X2h = (__half*)(sm2 + X2H_OFF);
    __half* Kh  = (__half*)(sm2 + KH_OFF);
    __half* Kl  = (__half*)(sm2 + KL_OFF);
    float* wsh = (float*)(sm2 + FP_OFF);
    float* zp  = wsh + 128;
    float* zsh = zp + TT2 * 16;
    float* ssh = zsh + TT2;
    float* csh = ssh + TT2;

    int blk = blockIdx.x;
    int n = blk >> 4;          // head
    int tile = blk & 15;       // 256-token tile
    int b = n >> 4, h = n & 15;
    int l0 = tile * TT2;

    const float* qb = Q + ((size_t)b * Lsz + l0) * Esz + h * 64;
    int t = threadIdx.x;

    if (t < 128) wsh[t] = g_w[n * 128 + t];
    {
        int l = l0 + t;
        float ang = 1.5707963267948966f * (float)(l + 1) / (float)Lsz;
        ssh[t] = sinf(ang);
        csh[t] = cosf(ang);
    }
    for (int idx = t; idx < 2048; idx += 256) {
        int mr = idx >> 5, c = idx & 31;
        *(uint2*)&Kh[mr * FS2 + c * 4] =
            *(const uint2*)&g_kvt_h[(size_t)n * 8192 + mr * 128 + c * 4];
        *(uint2*)&Kl[mr * FS2 + c * 4] =
            *(const uint2*)&g_kvt_l[(size_t)n * 8192 + mr * 128 + c * 4];
    }
    __syncthreads();

    // stage Rq (single fp16 plane) + exact fp32 z partials
    #pragma unroll
    for (int j = 0; j < 16; ++j) {
        int e4 = j * 256 + t;
        int tok = e4 >> 4;
        int ddg = (e4 & 15) * 4;
        float s = ssh[tok], c = csh[tok];
        float4 q4 = *(const float4*)&qb[(size_t)tok * Esz + ddg];
        float rq[4] = { fmaxf(q4.x, 0.f), fmaxf(q4.y, 0.f),
                        fmaxf(q4.z, 0.f), fmaxf(q4.w, 0.f) };
        float xs[4], xc[4];
        float zpart = 0.f;
        #pragma unroll
        for (int i = 0; i < 4; ++i) {
            xs[i] = rq[i] * s; xc[i] = rq[i] * c;
            zpart += xs[i] * wsh[ddg + i] + xc[i] * wsh[64 + ddg + i];
        }
        *(uint2*)&X2h[tok * FS2 + ddg] =
            make_uint2(pk16(xs[0], xs[1]), pk16(xs[2], xs[3]));
        *(uint2*)&X2h[tok * FS2 + 64 + ddg] =
            make_uint2(pk16(xc[0], xc[1]), pk16(xc[2], xc[3]));
        zp[tok * 16 + (e4 & 15)] = zpart;
    }
    __syncthreads();
    {
        float a = 0.f;
        #pragma unroll
        for (int g = 0; g < 16; ++g) a += zp[t * 16 + g];
        zsh[t] = 1.f / fmaxf(a, 1e-6f);
    }
    __syncthreads();

    int w = t >> 5, lane = t & 31;
    int gid = lane >> 2, tid = lane & 3;
    int tgw = w >> 1;          // token group: 64 tokens
    int mgw = w & 1;           // m group: 32 m
    int t0 = tgw * 64;
    int rn = lane & 15;
    int cn = ((lane >> 4) & 1) * 8;

    float acc[4][4][4];
    #pragma unroll
    for (int i = 0; i < 4; ++i)
        #pragma unroll
        for (int j = 0; j < 4; ++j)
            #pragma unroll
            for (int q = 0; q < 4; ++q) acc[i][j][q] = 0.f;

    #pragma unroll
    for (int ko = 0; ko < 128; ko += 16) {
        u32 ah[4][4];
        #pragma unroll
        for (int i = 0; i < 4; ++i)
            ldsm4(ah[i], sh_addr(&X2h[(t0 + i * 16 + rn) * FS2 + ko + cn]));
        #pragma unroll
        for (int jpl = 0; jpl < 2; ++jpl) {
            int jp = mgw * 2 + jpl;
            u32 bh[4], bl[4];
            ldsm4(bh, sh_addr(&Kh[(jp * 16 + rn) * FS2 + ko + cn]));
            ldsm4(bl, sh_addr(&Kl[(jp * 16 + rn) * FS2 + ko + cn]));
            #pragma unroll
            for (int i = 0; i < 4; ++i) {
                mma_f16(acc[i][2 * jpl],     ah[i], bh[0], bh[2]);
                mma_f16(acc[i][2 * jpl],     ah[i], bl[0], bl[2]);
                mma_f16(acc[i][2 * jpl + 1], ah[i], bh[1], bh[3]);
                mma_f16(acc[i][2 * jpl + 1], ah[i], bl[1], bl[3]);
            }
        }
    }

    float* ob = O + ((size_t)n * Lsz + l0) * 64;
    #pragma unroll
    for (int i = 0; i < 4; ++i) {
        int r1 = t0 + i * 16 + gid;
        float z1 = zsh[r1], z2 = zsh[r1 + 8];
        #pragma unroll
        for (int j = 0; j < 4; ++j) {
            int nb = mgw * 32 + j * 8 + tid * 2;
            *(float2*)&ob[(size_t)r1 * 64 + nb] =
                make_float2(acc[i][j][0] * z1, acc[i][j][1] * z1);
            *(float2*)&ob[(size_t)(r1 + 8) * 64 + nb] =
                make_float2(acc[i][j][2] * z2, acc[i][j][3] * z2);
        }
    }
}

// ---------------------------------------------------------------------------
extern "C" void kernel_launch(void* const* d_in, const int* in_sizes, int n_in,
                              void* d_out, int out_size) {
    const float* q = (const float*)d_in[0];
    const float* k = (const float*)d_in[1];
    const float* v = (const float*)d_in[2];
    const float* m = (const float*)d_in[3];
    float* out = (float*)d_out;

    cudaFuncSetAttribute(k_phase2, cudaFuncAttributeMaxDynamicSharedMemorySize,
                         SM2_BYTES);

    k_phase1<<<HEADS * SPLIT, 256>>>(k, v, m);
    k_reduce<<<HEADS * 4, 256>>>();
    k_phase2<<<HEADS * 16, 256, SM2_BYTES>>>(q, out);
}